// round 1
// baseline (speedup 1.0000x reference)
#include <cuda_runtime.h>

// Shapes: n=8, b=64, h=128, f=256, hs=64
#define N_SEQ 8
#define B_DIM 64
#define H_DIM 128
#define F_DIM 256
#define HS 64
#define M_TOTAL (N_SEQ * B_DIM * H_DIM)   // 65536 rows

// Device scratch for Q, K, V (each 65536 x 64 fp32 = 16 MB)
__device__ float g_Q[M_TOTAL * HS];
__device__ float g_K[M_TOTAL * HS];
__device__ float g_V[M_TOTAL * HS];

// ---------------------------------------------------------------------------
// Kernel A: QKV projection.  out = x (65536x256) @ W (256x64)
// grid (512, 3)  block 256.  128-row x 64-col tile, 8x4 micro-tile per thread.
// ---------------------------------------------------------------------------
__global__ __launch_bounds__(256) void qkv_kernel(
    const float* __restrict__ x,
    const float* __restrict__ Wq,
    const float* __restrict__ Wk,
    const float* __restrict__ Wv)
{
    __shared__ float xs[128][36];   // [row][k]   pad 36 (16B-aligned stride)
    __shared__ float wt[64][36];    // [col][k]   transposed W chunk

    const int t  = threadIdx.x;
    const int ty = t >> 4;          // 0..15 row group
    const int tx = t & 15;          // 0..15 col group
    const int rowBase = blockIdx.x * 128;
    const int w = blockIdx.y;
    const float* __restrict__ W = (w == 0) ? Wq : (w == 1) ? Wk : Wv;
    float* __restrict__ out = (w == 0) ? g_Q : (w == 1) ? g_K : g_V;

    float acc[8][4];
#pragma unroll
    for (int r = 0; r < 8; r++)
#pragma unroll
        for (int c = 0; c < 4; c++) acc[r][c] = 0.f;

    for (int k0 = 0; k0 < F_DIM; k0 += 32) {
        // load x tile 128x32 (coalesced float4)
        {
            int lrow = t >> 3;            // 0..31
            int lcol = (t & 7) * 4;       // 0..28
#pragma unroll
            for (int p = 0; p < 4; p++) {
                int row = p * 32 + lrow;
                float4 v = *(const float4*)&x[(size_t)(rowBase + row) * F_DIM + k0 + lcol];
                *(float4*)&xs[row][lcol] = v;
            }
        }
        // load W chunk transposed: wt[col][k] = W[k0+k][col]
        {
            int kr = t >> 4;              // 0..15
            int cg = (t & 15) * 4;        // 0..60
#pragma unroll
            for (int p = 0; p < 2; p++) {
                int k = p * 16 + kr;
                float4 v = *(const float4*)&W[(size_t)(k0 + k) * HS + cg];
                wt[cg + 0][k] = v.x;
                wt[cg + 1][k] = v.y;
                wt[cg + 2][k] = v.z;
                wt[cg + 3][k] = v.w;
            }
        }
        __syncthreads();

#pragma unroll
        for (int kk = 0; kk < 32; kk += 4) {
            float4 a[8];
#pragma unroll
            for (int r = 0; r < 8; r++)
                a[r] = *(const float4*)&xs[ty * 8 + r][kk];
            float4 bw[4];
#pragma unroll
            for (int c = 0; c < 4; c++)
                bw[c] = *(const float4*)&wt[tx * 4 + c][kk];
#pragma unroll
            for (int r = 0; r < 8; r++)
#pragma unroll
                for (int c = 0; c < 4; c++) {
                    acc[r][c] = fmaf(a[r].x, bw[c].x, acc[r][c]);
                    acc[r][c] = fmaf(a[r].y, bw[c].y, acc[r][c]);
                    acc[r][c] = fmaf(a[r].z, bw[c].z, acc[r][c]);
                    acc[r][c] = fmaf(a[r].w, bw[c].w, acc[r][c]);
                }
        }
        __syncthreads();
    }

#pragma unroll
    for (int r = 0; r < 8; r++) {
        int row = rowBase + ty * 8 + r;
        float4 v = make_float4(acc[r][0], acc[r][1], acc[r][2], acc[r][3]);
        *(float4*)&out[(size_t)row * HS + tx * 4] = v;
    }
}

// ---------------------------------------------------------------------------
// Kernel B: attention. One CTA per (j, b).  O[p,d] = sum_i softmax(Q_j K_i^T /16) V_i
// block 256 threads. Q tile resident; loop over i loading K_i, V_i.
// S: 8x8 micro-tile; PV: 8x4 micro-tile, O accum in registers across i.
// ---------------------------------------------------------------------------
#define QKV_STRIDE 68    // 128x64 tiles padded
#define SS_STRIDE 132    // 128x128 score tile padded

__global__ __launch_bounds__(256) void attn_kernel(float* __restrict__ out)
{
    extern __shared__ float smem[];
    float* qs = smem;                           // [128][68]
    float* ks = qs + 128 * QKV_STRIDE;          // [128][68]
    float* vs = ks + 128 * QKV_STRIDE;          // [128][68]
    float* ss = vs + 128 * QKV_STRIDE;          // [128][132]

    const int t  = threadIdx.x;
    const int ty = t >> 4;      // 0..15
    const int tx = t & 15;      // 0..15
    const int b  = blockIdx.x >> 3;
    const int j  = blockIdx.x & 7;
    const int qbase = (j * B_DIM + b) * H_DIM;  // row base into g_Q / out
    const float scale = 0.0625f;                // 256^-0.5

    // load Q tile (pre-scaled)
    for (int e = t; e < 2048; e += 256) {
        int row = e >> 4;
        int cg  = (e & 15) * 4;
        float4 v = *(const float4*)&g_Q[(size_t)(qbase + row) * HS + cg];
        v.x *= scale; v.y *= scale; v.z *= scale; v.w *= scale;
        *(float4*)&qs[row * QKV_STRIDE + cg] = v;
    }

    float oacc[8][4];
#pragma unroll
    for (int r = 0; r < 8; r++)
#pragma unroll
        for (int c = 0; c < 4; c++) oacc[r][c] = 0.f;

    for (int i = 0; i < N_SEQ; i++) {
        __syncthreads();   // prev PV done before overwriting ks/vs/ss (also covers qs on i=0)
        const int kbase = (i * B_DIM + b) * H_DIM;
        for (int e = t; e < 2048; e += 256) {
            int row = e >> 4;
            int cg  = (e & 15) * 4;
            *(float4*)&ks[row * QKV_STRIDE + cg] =
                *(const float4*)&g_K[(size_t)(kbase + row) * HS + cg];
            *(float4*)&vs[row * QKV_STRIDE + cg] =
                *(const float4*)&g_V[(size_t)(kbase + row) * HS + cg];
        }
        __syncthreads();

        // S[p][q] = sum_d qs[p][d] * ks[q][d]
        {
            float s[8][8];
#pragma unroll
            for (int r = 0; r < 8; r++)
#pragma unroll
                for (int c = 0; c < 8; c++) s[r][c] = 0.f;

            for (int d = 0; d < HS; d += 4) {
                float4 qa[8];
#pragma unroll
                for (int r = 0; r < 8; r++)
                    qa[r] = *(const float4*)&qs[(ty * 8 + r) * QKV_STRIDE + d];
                float4 kb[8];
#pragma unroll
                for (int c = 0; c < 8; c++)
                    kb[c] = *(const float4*)&ks[(tx * 8 + c) * QKV_STRIDE + d];
#pragma unroll
                for (int r = 0; r < 8; r++)
#pragma unroll
                    for (int c = 0; c < 8; c++) {
                        s[r][c] = fmaf(qa[r].x, kb[c].x, s[r][c]);
                        s[r][c] = fmaf(qa[r].y, kb[c].y, s[r][c]);
                        s[r][c] = fmaf(qa[r].z, kb[c].z, s[r][c]);
                        s[r][c] = fmaf(qa[r].w, kb[c].w, s[r][c]);
                    }
            }
#pragma unroll
            for (int r = 0; r < 8; r++) {
                float* row = &ss[(ty * 8 + r) * SS_STRIDE + tx * 8];
                *(float4*)&row[0] = make_float4(s[r][0], s[r][1], s[r][2], s[r][3]);
                *(float4*)&row[4] = make_float4(s[r][4], s[r][5], s[r][6], s[r][7]);
            }
        }
        __syncthreads();

        // softmax over q (row of 128), 2 threads per row
        {
            int row = t >> 1;
            int off = (t & 1) * 64;
            float* sr = &ss[row * SS_STRIDE + off];
            float m = -1e30f;
#pragma unroll
            for (int c = 0; c < 64; c += 4) {
                float4 v = *(const float4*)&sr[c];
                m = fmaxf(m, fmaxf(fmaxf(v.x, v.y), fmaxf(v.z, v.w)));
            }
            m = fmaxf(m, __shfl_xor_sync(0xffffffffu, m, 1));
            float sum = 0.f;
#pragma unroll
            for (int c = 0; c < 64; c += 4) {
                float4 v = *(const float4*)&sr[c];
                v.x = __expf(v.x - m); v.y = __expf(v.y - m);
                v.z = __expf(v.z - m); v.w = __expf(v.w - m);
                *(float4*)&sr[c] = v;
                sum += (v.x + v.y) + (v.z + v.w);
            }
            sum += __shfl_xor_sync(0xffffffffu, sum, 1);
            float inv = 1.0f / sum;
#pragma unroll
            for (int c = 0; c < 64; c += 4) {
                float4 v = *(const float4*)&sr[c];
                v.x *= inv; v.y *= inv; v.z *= inv; v.w *= inv;
                *(float4*)&sr[c] = v;
            }
        }
        __syncthreads();

        // O[p][d] += sum_q P[p][q] * V[q][d]
        for (int q = 0; q < 128; q += 4) {
            float4 pr[8];
#pragma unroll
            for (int r = 0; r < 8; r++)
                pr[r] = *(const float4*)&ss[(ty * 8 + r) * SS_STRIDE + q];
            float4 v0 = *(const float4*)&vs[(q + 0) * QKV_STRIDE + tx * 4];
            float4 v1 = *(const float4*)&vs[(q + 1) * QKV_STRIDE + tx * 4];
            float4 v2 = *(const float4*)&vs[(q + 2) * QKV_STRIDE + tx * 4];
            float4 v3 = *(const float4*)&vs[(q + 3) * QKV_STRIDE + tx * 4];
#pragma unroll
            for (int r = 0; r < 8; r++) {
                float4 p4 = pr[r];
                oacc[r][0] = fmaf(p4.x, v0.x, fmaf(p4.y, v1.x, fmaf(p4.z, v2.x, fmaf(p4.w, v3.x, oacc[r][0]))));
                oacc[r][1] = fmaf(p4.x, v0.y, fmaf(p4.y, v1.y, fmaf(p4.z, v2.y, fmaf(p4.w, v3.y, oacc[r][1]))));
                oacc[r][2] = fmaf(p4.x, v0.z, fmaf(p4.y, v1.z, fmaf(p4.z, v2.z, fmaf(p4.w, v3.z, oacc[r][2]))));
                oacc[r][3] = fmaf(p4.x, v0.w, fmaf(p4.y, v1.w, fmaf(p4.z, v2.w, fmaf(p4.w, v3.w, oacc[r][3]))));
            }
        }
    }

#pragma unroll
    for (int r = 0; r < 8; r++) {
        int p = ty * 8 + r;
        float4 v = make_float4(oacc[r][0], oacc[r][1], oacc[r][2], oacc[r][3]);
        *(float4*)&out[(size_t)(qbase + p) * HS + tx * 4] = v;
    }
}

// ---------------------------------------------------------------------------
extern "C" void kernel_launch(void* const* d_in, const int* in_sizes, int n_in,
                              void* d_out, int out_size)
{
    const float* x  = (const float*)d_in[0];
    const float* Wq = (const float*)d_in[1];
    const float* Wk = (const float*)d_in[2];
    const float* Wv = (const float*)d_in[3];
    float* out = (float*)d_out;

    qkv_kernel<<<dim3(512, 3), 256>>>(x, Wq, Wk, Wv);

    size_t smemB = (size_t)(3 * 128 * QKV_STRIDE + 128 * SS_STRIDE) * sizeof(float);
    cudaFuncSetAttribute(attn_kernel, cudaFuncAttributeMaxDynamicSharedMemorySize,
                         (int)smemB);
    attn_kernel<<<512, 256, smemB>>>(out);
}

// round 2
// speedup vs baseline: 1.7007x; 1.7007x over previous
#include <cuda_runtime.h>

// Shapes: n=8, b=64, h=128, f=256, hs=64
#define N_SEQ 8
#define B_DIM 64
#define H_DIM 128
#define F_DIM 256
#define HS 64
#define M_TOTAL (N_SEQ * B_DIM * H_DIM)   // 65536 rows

// Device scratch for Q, K, V (each 65536 x 64 fp32 = 16 MB)
__device__ float g_Q[M_TOTAL * HS];
__device__ float g_K[M_TOTAL * HS];
__device__ float g_V[M_TOTAL * HS];

// ---------------------------------------------------------------------------
// Kernel A: QKV projection.  out = x (65536x256) @ W (256x64)
// grid (512, 3)  block 256.  128-row x 64-col tile, 8x4 micro-tile per thread.
// Columns owned STRIDED: thread (ty,tx) owns cols {tx, tx+16, tx+32, tx+48}
// -> conflict-free W reads. Q is pre-scaled by 1/16.
// ---------------------------------------------------------------------------
__global__ __launch_bounds__(256) void qkv_kernel(
    const float* __restrict__ x,
    const float* __restrict__ Wq,
    const float* __restrict__ Wk,
    const float* __restrict__ Wv)
{
    __shared__ float xs[128][36];   // [row][k]
    __shared__ float ws[32][68];    // [k][col] (natural layout, padded)

    const int t  = threadIdx.x;
    const int ty = t >> 4;          // 0..15 row group
    const int tx = t & 15;          // 0..15 col group
    const int rowBase = blockIdx.x * 128;
    const int w = blockIdx.y;
    const float* __restrict__ W = (w == 0) ? Wq : (w == 1) ? Wk : Wv;
    float* __restrict__ out = (w == 0) ? g_Q : (w == 1) ? g_K : g_V;

    float acc[8][4];
#pragma unroll
    for (int r = 0; r < 8; r++)
#pragma unroll
        for (int c = 0; c < 4; c++) acc[r][c] = 0.f;

    for (int k0 = 0; k0 < F_DIM; k0 += 32) {
        // load x tile 128x32 (coalesced float4)
        {
            int lrow = t >> 3;            // 0..31
            int lcol = (t & 7) * 4;       // 0..28
#pragma unroll
            for (int p = 0; p < 4; p++) {
                int row = p * 32 + lrow;
                float4 v = *(const float4*)&x[(size_t)(rowBase + row) * F_DIM + k0 + lcol];
                *(float4*)&xs[row][lcol] = v;
            }
        }
        // load W chunk natural layout: ws[k][col]
        {
            int kr = t >> 4;              // 0..15
            int cg = (t & 15) * 4;        // 0..60
#pragma unroll
            for (int p = 0; p < 2; p++) {
                int k = p * 16 + kr;
                float4 v = *(const float4*)&W[(size_t)(k0 + k) * HS + cg];
                *(float4*)&ws[k][cg] = v;
            }
        }
        __syncthreads();

#pragma unroll
        for (int kk = 0; kk < 32; kk += 4) {
            float4 a[8];
#pragma unroll
            for (int r = 0; r < 8; r++)
                a[r] = *(const float4*)&xs[ty * 8 + r][kk];
            float bw[4][4];   // [c][e] = W[kk+e][tx + 16c]  (broadcast, conflict-free)
#pragma unroll
            for (int c = 0; c < 4; c++)
#pragma unroll
                for (int e = 0; e < 4; e++)
                    bw[c][e] = ws[kk + e][tx + 16 * c];
#pragma unroll
            for (int r = 0; r < 8; r++)
#pragma unroll
                for (int c = 0; c < 4; c++) {
                    acc[r][c] = fmaf(a[r].x, bw[c][0], acc[r][c]);
                    acc[r][c] = fmaf(a[r].y, bw[c][1], acc[r][c]);
                    acc[r][c] = fmaf(a[r].z, bw[c][2], acc[r][c]);
                    acc[r][c] = fmaf(a[r].w, bw[c][3], acc[r][c]);
                }
        }
        __syncthreads();
    }

    const float oscale = (w == 0) ? 0.0625f : 1.0f;   // fold 256^-0.5 into Q
#pragma unroll
    for (int r = 0; r < 8; r++) {
        size_t row = (size_t)(rowBase + ty * 8 + r) * HS;
#pragma unroll
        for (int c = 0; c < 4; c++)
            out[row + tx + 16 * c] = acc[r][c] * oscale;
    }
}

// ---------------------------------------------------------------------------
// Kernel B: attention. Grid 1024 = (j, b, half): each CTA owns 64 query rows.
// O[p,d] = sum_i softmax_q(Q_j K_i^T) V_i
// S micro-tile 4x8 with STRIDED q columns (q = cc*16 + tx) -> 2-way max on K
// reads. Softmax fully in registers via 16-lane shfl groups; normalized P
// written to smem once (conflict-free scalar stores).
// ---------------------------------------------------------------------------
#define KV_STR 68
#define Q_STR  68
#define SS_STR 132

__global__ __launch_bounds__(256) void attn_kernel(float* __restrict__ out)
{
    extern __shared__ float smem[];
    float* qs = smem;                     // [64][Q_STR]
    float* ks = qs + 64 * Q_STR;          // [128][KV_STR]
    float* vs = ks + 128 * KV_STR;        // [128][KV_STR]
    float* ss = vs + 128 * KV_STR;        // [64][SS_STR]

    const int t   = threadIdx.x;
    const int ty  = t >> 4;               // 0..15
    const int tx  = t & 15;               // 0..15
    const int j    = blockIdx.x & 7;
    const int b    = (blockIdx.x >> 3) & 63;
    const int half = blockIdx.x >> 9;     // 0/1
    const int qrow = (j * B_DIM + b) * H_DIM + half * 64;

    // load Q tile (already scaled by 1/16 in qkv_kernel)
    for (int e = t; e < 64 * 16; e += 256) {
        int row = e >> 4;
        int cg  = (e & 15) * 4;
        *(float4*)&qs[row * Q_STR + cg] =
            *(const float4*)&g_Q[(size_t)(qrow + row) * HS + cg];
    }

    float oacc[4][4];
#pragma unroll
    for (int r = 0; r < 4; r++)
#pragma unroll
        for (int c = 0; c < 4; c++) oacc[r][c] = 0.f;

    for (int i = 0; i < N_SEQ; i++) {
        __syncthreads();   // prev PV done before overwriting ks/vs/ss
        const int kb0 = (i * B_DIM + b) * H_DIM;
        for (int e = t; e < 128 * 16; e += 256) {
            int row = e >> 4;
            int cg  = (e & 15) * 4;
            *(float4*)&ks[row * KV_STR + cg] =
                *(const float4*)&g_K[(size_t)(kb0 + row) * HS + cg];
            *(float4*)&vs[row * KV_STR + cg] =
                *(const float4*)&g_V[(size_t)(kb0 + row) * HS + cg];
        }
        __syncthreads();

        // S[p][q], p = ty*4+r, q = cc*16+tx
        float s[4][8];
#pragma unroll
        for (int r = 0; r < 4; r++)
#pragma unroll
            for (int c = 0; c < 8; c++) s[r][c] = 0.f;

#pragma unroll 4
        for (int d = 0; d < HS; d += 4) {
            float4 qa[4];
#pragma unroll
            for (int r = 0; r < 4; r++)
                qa[r] = *(const float4*)&qs[(ty * 4 + r) * Q_STR + d];
            float4 kb[8];
#pragma unroll
            for (int c = 0; c < 8; c++)
                kb[c] = *(const float4*)&ks[(c * 16 + tx) * KV_STR + d];
#pragma unroll
            for (int r = 0; r < 4; r++)
#pragma unroll
                for (int c = 0; c < 8; c++) {
                    s[r][c] = fmaf(qa[r].x, kb[c].x, s[r][c]);
                    s[r][c] = fmaf(qa[r].y, kb[c].y, s[r][c]);
                    s[r][c] = fmaf(qa[r].z, kb[c].z, s[r][c]);
                    s[r][c] = fmaf(qa[r].w, kb[c].w, s[r][c]);
                }
        }

        // Register softmax: row p is owned by the 16 lanes sharing ty.
        // xor masks 1,2,4,8 stay inside the 16-lane group.
#pragma unroll
        for (int r = 0; r < 4; r++) {
            float m = s[r][0];
#pragma unroll
            for (int c = 1; c < 8; c++) m = fmaxf(m, s[r][c]);
#pragma unroll
            for (int msk = 1; msk < 16; msk <<= 1)
                m = fmaxf(m, __shfl_xor_sync(0xffffffffu, m, msk));
            float sum = 0.f;
#pragma unroll
            for (int c = 0; c < 8; c++) {
                s[r][c] = __expf(s[r][c] - m);
                sum += s[r][c];
            }
#pragma unroll
            for (int msk = 1; msk < 16; msk <<= 1)
                sum += __shfl_xor_sync(0xffffffffu, sum, msk);
            float inv = 1.0f / sum;
            float* srow = &ss[(ty * 4 + r) * SS_STR + tx];
#pragma unroll
            for (int c = 0; c < 8; c++)
                srow[c * 16] = s[r][c] * inv;
        }
        __syncthreads();

        // O[p][d] += sum_q P[p][q] * V[q][d]   (d cols = tx*4..tx*4+3)
#pragma unroll 2
        for (int q = 0; q < 128; q += 4) {
            float4 pr[4];
#pragma unroll
            for (int r = 0; r < 4; r++)
                pr[r] = *(const float4*)&ss[(ty * 4 + r) * SS_STR + q];
            float4 v0 = *(const float4*)&vs[(q + 0) * KV_STR + tx * 4];
            float4 v1 = *(const float4*)&vs[(q + 1) * KV_STR + tx * 4];
            float4 v2 = *(const float4*)&vs[(q + 2) * KV_STR + tx * 4];
            float4 v3 = *(const float4*)&vs[(q + 3) * KV_STR + tx * 4];
#pragma unroll
            for (int r = 0; r < 4; r++) {
                float4 p4 = pr[r];
                oacc[r][0] = fmaf(p4.x, v0.x, fmaf(p4.y, v1.x, fmaf(p4.z, v2.x, fmaf(p4.w, v3.x, oacc[r][0]))));
                oacc[r][1] = fmaf(p4.x, v0.y, fmaf(p4.y, v1.y, fmaf(p4.z, v2.y, fmaf(p4.w, v3.y, oacc[r][1]))));
                oacc[r][2] = fmaf(p4.x, v0.z, fmaf(p4.y, v1.z, fmaf(p4.z, v2.z, fmaf(p4.w, v3.z, oacc[r][2]))));
                oacc[r][3] = fmaf(p4.x, v0.w, fmaf(p4.y, v1.w, fmaf(p4.z, v2.w, fmaf(p4.w, v3.w, oacc[r][3]))));
            }
        }
    }

#pragma unroll
    for (int r = 0; r < 4; r++) {
        int p = ty * 4 + r;
        float4 v = make_float4(oacc[r][0], oacc[r][1], oacc[r][2], oacc[r][3]);
        *(float4*)&out[(size_t)(qrow + p) * HS + tx * 4] = v;
    }
}

// ---------------------------------------------------------------------------
extern "C" void kernel_launch(void* const* d_in, const int* in_sizes, int n_in,
                              void* d_out, int out_size)
{
    const float* x  = (const float*)d_in[0];
    const float* Wq = (const float*)d_in[1];
    const float* Wk = (const float*)d_in[2];
    const float* Wv = (const float*)d_in[3];
    float* out = (float*)d_out;

    qkv_kernel<<<dim3(512, 3), 256>>>(x, Wq, Wk, Wv);

    size_t smemB = (size_t)(64 * Q_STR + 2 * 128 * KV_STR + 64 * SS_STR) * sizeof(float);
    cudaFuncSetAttribute(attn_kernel, cudaFuncAttributeMaxDynamicSharedMemorySize,
                         (int)smemB);
    attn_kernel<<<1024, 256, smemB>>>(out);
}

// round 5
// speedup vs baseline: 2.4517x; 1.4415x over previous
#include <cuda_runtime.h>
#include <cuda_bf16.h>
#include <mma.h>
#include <cstdint>

using namespace nvcuda;

// Shapes: n=8, b=64, h=128, f=256, hs=64
#define N_SEQ 8
#define B_DIM 64
#define H_DIM 128
#define F_DIM 256
#define HS 64
#define M_TOTAL (N_SEQ * B_DIM * H_DIM)   // 65536 rows

__device__ float g_Q[M_TOTAL * HS];
__device__ float g_K[M_TOTAL * HS];
__device__ float g_V[M_TOTAL * HS];

typedef wmma::fragment<wmma::matrix_a, 16, 16, 16, __nv_bfloat16, wmma::row_major> FragA;
typedef wmma::fragment<wmma::matrix_b, 16, 16, 16, __nv_bfloat16, wmma::row_major> FragB;
typedef wmma::fragment<wmma::matrix_b, 16, 16, 16, __nv_bfloat16, wmma::col_major> FragBT;
typedef wmma::fragment<wmma::accumulator, 16, 16, 16, float> FragC;

__device__ __forceinline__ void split2(float x, __nv_bfloat16& h, __nv_bfloat16& l) {
    h = __float2bfloat16(x);
    l = __float2bfloat16(x - __bfloat162float(h));
}

// ---------------------------------------------------------------------------
// Kernel A: QKV via bf16 wmma split-3. grid (1024,3), block 256.
// Per CTA 64 rows x 64 cols, K chunks of 32 (2 wmma k-steps).
// Warps 4M x 2N. Strides: xs 40 (80B, odd 16B multiple), ws 72 (144B).
// ---------------------------------------------------------------------------
#define XSTR 40
#define WSTR 72

__global__ __launch_bounds__(256) void qkv_kernel(
    const float* __restrict__ x,
    const float* __restrict__ Wq,
    const float* __restrict__ Wk,
    const float* __restrict__ Wv)
{
    __shared__ __nv_bfloat16 xs_hi[64][XSTR], xs_lo[64][XSTR];
    __shared__ __nv_bfloat16 ws_hi[32][WSTR], ws_lo[32][WSTR];

    const int t  = threadIdx.x;
    const int w  = t >> 5;
    const int wm = w >> 1;          // 0..3
    const int wn = w & 1;           // 0..1
    const int rowBase = blockIdx.x * 64;
    const int which = blockIdx.y;
    const float* __restrict__ W = (which == 0) ? Wq : (which == 1) ? Wk : Wv;
    float* __restrict__ out = (which == 0) ? g_Q : (which == 1) ? g_K : g_V;
    const float inScale = (which == 0) ? 0.0625f : 1.0f;   // fold 256^-0.5 into Q

    FragC acc[2];
    wmma::fill_fragment(acc[0], 0.0f);
    wmma::fill_fragment(acc[1], 0.0f);

    for (int k0 = 0; k0 < F_DIM; k0 += 32) {
        // x tile 64x32 -> bf16 hi/lo (scaled)
#pragma unroll
        for (int p = 0; p < 2; p++) {
            int e = t + p * 256;
            int row = e >> 3;
            int lc  = (e & 7) * 4;
            float4 v = *(const float4*)&x[(size_t)(rowBase + row) * F_DIM + k0 + lc];
            v.x *= inScale; v.y *= inScale; v.z *= inScale; v.w *= inScale;
            __nv_bfloat16 h0,l0,h1,l1,h2,l2,h3,l3;
            split2(v.x,h0,l0); split2(v.y,h1,l1); split2(v.z,h2,l2); split2(v.w,h3,l3);
            *(__nv_bfloat162*)&xs_hi[row][lc]     = __nv_bfloat162(h0, h1);
            *(__nv_bfloat162*)&xs_hi[row][lc + 2] = __nv_bfloat162(h2, h3);
            *(__nv_bfloat162*)&xs_lo[row][lc]     = __nv_bfloat162(l0, l1);
            *(__nv_bfloat162*)&xs_lo[row][lc + 2] = __nv_bfloat162(l2, l3);
        }
        // W chunk 32x64 -> bf16 hi/lo
#pragma unroll
        for (int p = 0; p < 2; p++) {
            int e = t + p * 256;
            int k  = e >> 4;
            int cg = (e & 15) * 4;
            float4 v = *(const float4*)&W[(size_t)(k0 + k) * HS + cg];
            __nv_bfloat16 h0,l0,h1,l1,h2,l2,h3,l3;
            split2(v.x,h0,l0); split2(v.y,h1,l1); split2(v.z,h2,l2); split2(v.w,h3,l3);
            *(__nv_bfloat162*)&ws_hi[k][cg]     = __nv_bfloat162(h0, h1);
            *(__nv_bfloat162*)&ws_hi[k][cg + 2] = __nv_bfloat162(h2, h3);
            *(__nv_bfloat162*)&ws_lo[k][cg]     = __nv_bfloat162(l0, l1);
            *(__nv_bfloat162*)&ws_lo[k][cg + 2] = __nv_bfloat162(l2, l3);
        }
        __syncthreads();

#pragma unroll
        for (int kk = 0; kk < 32; kk += 16) {
            FragA a_hi, a_lo;
            wmma::load_matrix_sync(a_hi, &xs_hi[wm * 16][kk], XSTR);
            wmma::load_matrix_sync(a_lo, &xs_lo[wm * 16][kk], XSTR);
#pragma unroll
            for (int nt = 0; nt < 2; nt++) {
                FragB b_hi, b_lo;
                wmma::load_matrix_sync(b_hi, &ws_hi[kk][wn * 32 + nt * 16], WSTR);
                wmma::load_matrix_sync(b_lo, &ws_lo[kk][wn * 32 + nt * 16], WSTR);
                wmma::mma_sync(acc[nt], a_hi, b_hi, acc[nt]);
                wmma::mma_sync(acc[nt], a_hi, b_lo, acc[nt]);
                wmma::mma_sync(acc[nt], a_lo, b_hi, acc[nt]);
            }
        }
        __syncthreads();
    }

#pragma unroll
    for (int nt = 0; nt < 2; nt++)
        wmma::store_matrix_sync(&out[(size_t)(rowBase + wm * 16) * HS + wn * 32 + nt * 16],
                                acc[nt], HS, wmma::mem_row_major);
}

// ---------------------------------------------------------------------------
// Kernel B: attention. Grid 1024 = (j,b,half): 64 q rows per CTA, 8 warps.
// S = QK^T split-3 bf16 wmma (K col_major), fp32 S in smem, shfl softmax,
// P split to bf16 hi/lo, O += PV split-3 wmma (acc frags persist over i).
// Strides (bf16): qs/ks/vs 72 (144B), ps 136 (272B); ss fp32 132 (528B).
// ---------------------------------------------------------------------------
#define QKSTR 72
#define PBSTR 136
#define SSTR  132

__global__ __launch_bounds__(256) void attn_kernel(float* __restrict__ out)
{
    extern __shared__ float smem[];
    float* ss = smem;                                  // [64][132] fp32
    __nv_bfloat16* bbase = (__nv_bfloat16*)(smem + 64 * SSTR);
    __nv_bfloat16* qs_hi = bbase;                      // [64][72]
    __nv_bfloat16* qs_lo = qs_hi + 64 * QKSTR;
    __nv_bfloat16* ks_hi = qs_lo + 64 * QKSTR;         // [128][72]
    __nv_bfloat16* ks_lo = ks_hi + 128 * QKSTR;
    __nv_bfloat16* vs_hi = ks_lo + 128 * QKSTR;        // [128][72]
    __nv_bfloat16* vs_lo = vs_hi + 128 * QKSTR;
    __nv_bfloat16* ps_hi = vs_lo + 128 * QKSTR;        // [64][136]
    __nv_bfloat16* ps_lo = ps_hi + 64 * PBSTR;

    const int t  = threadIdx.x;
    const int w  = t >> 5;
    const int wm = w >> 1;         // 0..3 (16 rows each)
    const int wn = w & 1;          // 0..1
    const int j    = blockIdx.x & 7;
    const int b    = (blockIdx.x >> 3) & 63;
    const int half = blockIdx.x >> 9;
    const int qrow = (j * B_DIM + b) * H_DIM + half * 64;

    // load Q tile (pre-scaled by 1/16 in qkv), split to bf16 hi/lo
#pragma unroll
    for (int p = 0; p < 4; p++) {
        int e = t + p * 256;
        int row = e >> 4;
        int cg  = (e & 15) * 4;
        float4 v = *(const float4*)&g_Q[(size_t)(qrow + row) * HS + cg];
        __nv_bfloat16 h0,l0,h1,l1,h2,l2,h3,l3;
        split2(v.x,h0,l0); split2(v.y,h1,l1); split2(v.z,h2,l2); split2(v.w,h3,l3);
        *(__nv_bfloat162*)&qs_hi[row * QKSTR + cg]     = __nv_bfloat162(h0, h1);
        *(__nv_bfloat162*)&qs_hi[row * QKSTR + cg + 2] = __nv_bfloat162(h2, h3);
        *(__nv_bfloat162*)&qs_lo[row * QKSTR + cg]     = __nv_bfloat162(l0, l1);
        *(__nv_bfloat162*)&qs_lo[row * QKSTR + cg + 2] = __nv_bfloat162(l2, l3);
    }

    FragC oacc[2];
    wmma::fill_fragment(oacc[0], 0.0f);
    wmma::fill_fragment(oacc[1], 0.0f);

    for (int i = 0; i < N_SEQ; i++) {
        __syncthreads();   // prev PV done before overwriting ks/vs/ss; covers qs at i=0
        const int kb0 = (i * B_DIM + b) * H_DIM;
#pragma unroll
        for (int p = 0; p < 8; p++) {
            int e = t + p * 256;
            int row = e >> 4;
            int cg  = (e & 15) * 4;
            float4 kv = *(const float4*)&g_K[(size_t)(kb0 + row) * HS + cg];
            __nv_bfloat16 h0,l0,h1,l1,h2,l2,h3,l3;
            split2(kv.x,h0,l0); split2(kv.y,h1,l1); split2(kv.z,h2,l2); split2(kv.w,h3,l3);
            *(__nv_bfloat162*)&ks_hi[row * QKSTR + cg]     = __nv_bfloat162(h0, h1);
            *(__nv_bfloat162*)&ks_hi[row * QKSTR + cg + 2] = __nv_bfloat162(h2, h3);
            *(__nv_bfloat162*)&ks_lo[row * QKSTR + cg]     = __nv_bfloat162(l0, l1);
            *(__nv_bfloat162*)&ks_lo[row * QKSTR + cg + 2] = __nv_bfloat162(l2, l3);
            float4 vv = *(const float4*)&g_V[(size_t)(kb0 + row) * HS + cg];
            split2(vv.x,h0,l0); split2(vv.y,h1,l1); split2(vv.z,h2,l2); split2(vv.w,h3,l3);
            *(__nv_bfloat162*)&vs_hi[row * QKSTR + cg]     = __nv_bfloat162(h0, h1);
            *(__nv_bfloat162*)&vs_hi[row * QKSTR + cg + 2] = __nv_bfloat162(h2, h3);
            *(__nv_bfloat162*)&vs_lo[row * QKSTR + cg]     = __nv_bfloat162(l0, l1);
            *(__nv_bfloat162*)&vs_lo[row * QKSTR + cg + 2] = __nv_bfloat162(l2, l3);
        }
        __syncthreads();

        // ---- S = Q K^T : warp computes 16 rows x 64 q-cols (4 frags) ----
        {
            FragC sacc[4];
#pragma unroll
            for (int nt = 0; nt < 4; nt++) wmma::fill_fragment(sacc[nt], 0.0f);

#pragma unroll
            for (int d0 = 0; d0 < HS; d0 += 16) {
                FragA a_hi, a_lo;
                wmma::load_matrix_sync(a_hi, &qs_hi[(wm * 16) * QKSTR + d0], QKSTR);
                wmma::load_matrix_sync(a_lo, &qs_lo[(wm * 16) * QKSTR + d0], QKSTR);
#pragma unroll
                for (int nt = 0; nt < 4; nt++) {
                    int q0 = wn * 64 + nt * 16;
                    FragBT b_hi, b_lo;   // B[d][q] = K[q][d] -> col_major on K rows
                    wmma::load_matrix_sync(b_hi, &ks_hi[q0 * QKSTR + d0], QKSTR);
                    wmma::load_matrix_sync(b_lo, &ks_lo[q0 * QKSTR + d0], QKSTR);
                    wmma::mma_sync(sacc[nt], a_hi, b_hi, sacc[nt]);
                    wmma::mma_sync(sacc[nt], a_hi, b_lo, sacc[nt]);
                    wmma::mma_sync(sacc[nt], a_lo, b_hi, sacc[nt]);
                }
            }
#pragma unroll
            for (int nt = 0; nt < 4; nt++)
                wmma::store_matrix_sync(&ss[(wm * 16) * SSTR + wn * 64 + nt * 16],
                                        sacc[nt], SSTR, wmma::mem_row_major);
        }
        __syncthreads();

        // ---- softmax over q (128); P -> bf16 hi/lo ----
        {
            const int ty = t >> 4;
            const int tx = t & 15;
#pragma unroll
            for (int r = 0; r < 4; r++) {
                int row = ty * 4 + r;
                float* sr = &ss[row * SSTR];
                float v[8];
#pragma unroll
                for (int c = 0; c < 8; c++) v[c] = sr[c * 16 + tx];
                float m = v[0];
#pragma unroll
                for (int c = 1; c < 8; c++) m = fmaxf(m, v[c]);
#pragma unroll
                for (int msk = 1; msk < 16; msk <<= 1)
                    m = fmaxf(m, __shfl_xor_sync(0xffffffffu, m, msk));
                float sum = 0.f;
#pragma unroll
                for (int c = 0; c < 8; c++) { v[c] = __expf(v[c] - m); sum += v[c]; }
#pragma unroll
                for (int msk = 1; msk < 16; msk <<= 1)
                    sum += __shfl_xor_sync(0xffffffffu, sum, msk);
                float inv = 1.0f / sum;
#pragma unroll
                for (int c = 0; c < 8; c++) {
                    float p = v[c] * inv;
                    __nv_bfloat16 h, l;
                    split2(p, h, l);
                    ps_hi[row * PBSTR + c * 16 + tx] = h;
                    ps_lo[row * PBSTR + c * 16 + tx] = l;
                }
            }
        }
        __syncthreads();

        // ---- O += P V : warp 16 x 32 (2 frags), split-3, persists over i ----
#pragma unroll
        for (int kk = 0; kk < 128; kk += 16) {
            FragA a_hi, a_lo;
            wmma::load_matrix_sync(a_hi, &ps_hi[(wm * 16) * PBSTR + kk], PBSTR);
            wmma::load_matrix_sync(a_lo, &ps_lo[(wm * 16) * PBSTR + kk], PBSTR);
#pragma unroll
            for (int nt = 0; nt < 2; nt++) {
                FragB b_hi, b_lo;
                wmma::load_matrix_sync(b_hi, &vs_hi[kk * QKSTR + wn * 32 + nt * 16], QKSTR);
                wmma::load_matrix_sync(b_lo, &vs_lo[kk * QKSTR + wn * 32 + nt * 16], QKSTR);
                wmma::mma_sync(oacc[nt], a_hi, b_hi, oacc[nt]);
                wmma::mma_sync(oacc[nt], a_hi, b_lo, oacc[nt]);
                wmma::mma_sync(oacc[nt], a_lo, b_hi, oacc[nt]);
            }
        }
    }

#pragma unroll
    for (int nt = 0; nt < 2; nt++)
        wmma::store_matrix_sync(&out[(size_t)(qrow + wm * 16) * HS + wn * 32 + nt * 16],
                                oacc[nt], HS, wmma::mem_row_major);
}

// ---------------------------------------------------------------------------
extern "C" void kernel_launch(void* const* d_in, const int* in_sizes, int n_in,
                              void* d_out, int out_size)
{
    const float* x  = (const float*)d_in[0];
    const float* Wq = (const float*)d_in[1];
    const float* Wk = (const float*)d_in[2];
    const float* Wv = (const float*)d_in[3];
    float* out = (float*)d_out;

    qkv_kernel<<<dim3(1024, 3), 256>>>(x, Wq, Wk, Wv);

    size_t smemB = (size_t)64 * SSTR * sizeof(float)
                 + (size_t)(2 * 64 * QKSTR + 4 * 128 * QKSTR + 2 * 64 * PBSTR)
                   * sizeof(__nv_bfloat16);
    cudaFuncSetAttribute(attn_kernel, cudaFuncAttributeMaxDynamicSharedMemorySize,
                         (int)smemB);
    attn_kernel<<<1024, 256, smemB>>>(out);
}

// round 6
// speedup vs baseline: 2.4822x; 1.0124x over previous
#include <cuda_runtime.h>
#include <cuda_bf16.h>
#include <mma.h>
#include <cstdint>

using namespace nvcuda;

// Shapes: n=8, b=64, h=128, f=256, hs=64
#define N_SEQ 8
#define B_DIM 64
#define H_DIM 128
#define F_DIM 256
#define HS 64
#define M_TOTAL (N_SEQ * B_DIM * H_DIM)   // 65536 rows

// Pre-split bf16 hi/lo Q,K,V (Q pre-scaled by 1/16)
__device__ __nv_bfloat16 g_Qh[M_TOTAL * HS], g_Ql[M_TOTAL * HS];
__device__ __nv_bfloat16 g_Kh[M_TOTAL * HS], g_Kl[M_TOTAL * HS];
__device__ __nv_bfloat16 g_Vh[M_TOTAL * HS], g_Vl[M_TOTAL * HS];

typedef wmma::fragment<wmma::matrix_a, 16, 16, 16, __nv_bfloat16, wmma::row_major> FragA;
typedef wmma::fragment<wmma::matrix_b, 16, 16, 16, __nv_bfloat16, wmma::row_major> FragB;
typedef wmma::fragment<wmma::matrix_b, 16, 16, 16, __nv_bfloat16, wmma::col_major> FragBT;
typedef wmma::fragment<wmma::accumulator, 16, 16, 16, float> FragC;

__device__ __forceinline__ void split2(float x, __nv_bfloat16& h, __nv_bfloat16& l) {
    h = __float2bfloat16(x);
    l = __float2bfloat16(x - __bfloat162float(h));
}

// ---------------------------------------------------------------------------
// Kernel A: QKV via bf16 wmma split-3, outputs PRE-SPLIT bf16 hi/lo.
// grid (512, 3), block 512 (16 warps). Per CTA 128 rows x 64 cols, K chunks 32.
// Warps 8M x 2N (warp tile 16x32).
// ---------------------------------------------------------------------------
#define XSTR 40
#define WSTR 72

__global__ __launch_bounds__(512) void qkv_kernel(
    const float* __restrict__ x,
    const float* __restrict__ Wq,
    const float* __restrict__ Wk,
    const float* __restrict__ Wv)
{
    __shared__ __nv_bfloat16 xs_hi[128][XSTR], xs_lo[128][XSTR];
    __shared__ __nv_bfloat16 ws_hi[32][WSTR], ws_lo[32][WSTR];
    __shared__ float sbuf[16][16 * 20];   // per-warp epilogue staging

    const int t    = threadIdx.x;
    const int w    = t >> 5;
    const int lane = t & 31;
    const int wm   = w >> 1;        // 0..7
    const int wn   = w & 1;         // 0..1
    const int rowBase = blockIdx.x * 128;
    const int which = blockIdx.y;
    const float* __restrict__ W = (which == 0) ? Wq : (which == 1) ? Wk : Wv;
    __nv_bfloat16* __restrict__ outH = (which == 0) ? g_Qh : (which == 1) ? g_Kh : g_Vh;
    __nv_bfloat16* __restrict__ outL = (which == 0) ? g_Ql : (which == 1) ? g_Kl : g_Vl;
    const float inScale = (which == 0) ? 0.0625f : 1.0f;   // fold 256^-0.5 into Q

    FragC acc[2];
    wmma::fill_fragment(acc[0], 0.0f);
    wmma::fill_fragment(acc[1], 0.0f);

    for (int k0 = 0; k0 < F_DIM; k0 += 32) {
        // x tile 128x32 -> bf16 hi/lo (scaled)
#pragma unroll
        for (int p = 0; p < 2; p++) {
            int e = t + p * 512;
            int row = e >> 3;
            int lc  = (e & 7) * 4;
            float4 v = *(const float4*)&x[(size_t)(rowBase + row) * F_DIM + k0 + lc];
            v.x *= inScale; v.y *= inScale; v.z *= inScale; v.w *= inScale;
            __nv_bfloat16 h0,l0,h1,l1,h2,l2,h3,l3;
            split2(v.x,h0,l0); split2(v.y,h1,l1); split2(v.z,h2,l2); split2(v.w,h3,l3);
            *(__nv_bfloat162*)&xs_hi[row][lc]     = __nv_bfloat162(h0, h1);
            *(__nv_bfloat162*)&xs_hi[row][lc + 2] = __nv_bfloat162(h2, h3);
            *(__nv_bfloat162*)&xs_lo[row][lc]     = __nv_bfloat162(l0, l1);
            *(__nv_bfloat162*)&xs_lo[row][lc + 2] = __nv_bfloat162(l2, l3);
        }
        // W chunk 32x64 -> bf16 hi/lo
        {
            int k  = t >> 4;
            int cg = (t & 15) * 4;
            float4 v = *(const float4*)&W[(size_t)(k0 + k) * HS + cg];
            __nv_bfloat16 h0,l0,h1,l1,h2,l2,h3,l3;
            split2(v.x,h0,l0); split2(v.y,h1,l1); split2(v.z,h2,l2); split2(v.w,h3,l3);
            *(__nv_bfloat162*)&ws_hi[k][cg]     = __nv_bfloat162(h0, h1);
            *(__nv_bfloat162*)&ws_hi[k][cg + 2] = __nv_bfloat162(h2, h3);
            *(__nv_bfloat162*)&ws_lo[k][cg]     = __nv_bfloat162(l0, l1);
            *(__nv_bfloat162*)&ws_lo[k][cg + 2] = __nv_bfloat162(l2, l3);
        }
        __syncthreads();

#pragma unroll
        for (int kk = 0; kk < 32; kk += 16) {
            FragA a_hi, a_lo;
            wmma::load_matrix_sync(a_hi, &xs_hi[wm * 16][kk], XSTR);
            wmma::load_matrix_sync(a_lo, &xs_lo[wm * 16][kk], XSTR);
#pragma unroll
            for (int nt = 0; nt < 2; nt++) {
                FragB b_hi, b_lo;
                wmma::load_matrix_sync(b_hi, &ws_hi[kk][wn * 32 + nt * 16], WSTR);
                wmma::load_matrix_sync(b_lo, &ws_lo[kk][wn * 32 + nt * 16], WSTR);
                wmma::mma_sync(acc[nt], a_hi, b_hi, acc[nt]);
                wmma::mma_sync(acc[nt], a_hi, b_lo, acc[nt]);
                wmma::mma_sync(acc[nt], a_lo, b_hi, acc[nt]);
            }
        }
        __syncthreads();
    }

    // epilogue: stage fp32 in per-warp smem, split to bf16 hi/lo, store
#pragma unroll
    for (int nt = 0; nt < 2; nt++) {
        wmma::store_matrix_sync(&sbuf[w][0], acc[nt], 20, wmma::mem_row_major);
        __syncwarp();
        int r  = lane & 15;
        int cg = (lane >> 4) * 8;
        size_t gbase = (size_t)(rowBase + wm * 16 + r) * HS + wn * 32 + nt * 16 + cg;
        __nv_bfloat16 hh[8], ll[8];
#pragma unroll
        for (int c = 0; c < 8; c++)
            split2(sbuf[w][r * 20 + cg + c], hh[c], ll[c]);
#pragma unroll
        for (int c = 0; c < 8; c += 2) {
            *(__nv_bfloat162*)&outH[gbase + c] = __nv_bfloat162(hh[c], hh[c + 1]);
            *(__nv_bfloat162*)&outL[gbase + c] = __nv_bfloat162(ll[c], ll[c + 1]);
        }
        __syncwarp();
    }
}

// ---------------------------------------------------------------------------
// Kernel B: attention. Grid 1024 = (j,b,half), block 512 (16 warps).
// 64 q rows per CTA. S warps 4M x 4N (16x32, 2 frags); PV warps 4M x 4N
// (16x16, 1 persistent acc frag). Tiles are pure bf16 copies (pre-split).
// ---------------------------------------------------------------------------
#define QKSTR 72
#define PBSTR 136
#define SSTR  132

__global__ __launch_bounds__(512) void attn_kernel(float* __restrict__ out)
{
    extern __shared__ float smem[];
    float* ss = smem;                                  // [64][132] fp32
    __nv_bfloat16* bbase = (__nv_bfloat16*)(smem + 64 * SSTR);
    __nv_bfloat16* qs_hi = bbase;                      // [64][72]
    __nv_bfloat16* qs_lo = qs_hi + 64 * QKSTR;
    __nv_bfloat16* ks_hi = qs_lo + 64 * QKSTR;         // [128][72]
    __nv_bfloat16* ks_lo = ks_hi + 128 * QKSTR;
    __nv_bfloat16* vs_hi = ks_lo + 128 * QKSTR;        // [128][72]
    __nv_bfloat16* vs_lo = vs_hi + 128 * QKSTR;
    __nv_bfloat16* ps_hi = vs_lo + 128 * QKSTR;        // [64][136]
    __nv_bfloat16* ps_lo = ps_hi + 64 * PBSTR;

    const int t  = threadIdx.x;
    const int w  = t >> 5;
    const int wm = w >> 2;         // 0..3 (16 rows)
    const int wn = w & 3;          // 0..3
    const int j    = blockIdx.x & 7;
    const int b    = (blockIdx.x >> 3) & 63;
    const int half = blockIdx.x >> 9;
    const int qrow = (j * B_DIM + b) * H_DIM + half * 64;

    // load Q tile (pre-split bf16, pre-scaled): 64 rows x 64 = 8 uint4/row
    {
        int e = t;                  // 512 threads, 2 x 512 uint4 total
#pragma unroll
        for (int p = 0; p < 2; p++, e += 512) {
            int arr = e >> 9;       // 0: hi, 1: lo   (e < 1024)
            int idx = e & 511;
            int row = idx >> 3;
            int cg  = (idx & 7) * 8;
            const __nv_bfloat16* src = arr ? g_Ql : g_Qh;
            __nv_bfloat16* dst = arr ? qs_lo : qs_hi;
            *(uint4*)&dst[row * QKSTR + cg] =
                *(const uint4*)&src[(size_t)(qrow + row) * HS + cg];
        }
    }

    FragC oacc;
    wmma::fill_fragment(oacc, 0.0f);

    for (int i = 0; i < N_SEQ; i++) {
        __syncthreads();   // prev PV done before overwriting ks/vs/ss; covers qs at i=0
        const int kb0 = (i * B_DIM + b) * H_DIM;
        // copy K,V hi/lo: 4 arrays x 128 rows x 8 uint4 = 4096 uint4
        {
            int e = t;
#pragma unroll
            for (int p = 0; p < 8; p++, e += 512) {
                int arr = e >> 10;              // 0..3
                int idx = e & 1023;
                int row = idx >> 3;
                int cg  = (idx & 7) * 8;
                const __nv_bfloat16* src = (arr == 0) ? g_Kh : (arr == 1) ? g_Kl
                                          : (arr == 2) ? g_Vh : g_Vl;
                __nv_bfloat16* dst = (arr == 0) ? ks_hi : (arr == 1) ? ks_lo
                                    : (arr == 2) ? vs_hi : vs_lo;
                *(uint4*)&dst[row * QKSTR + cg] =
                    *(const uint4*)&src[(size_t)(kb0 + row) * HS + cg];
            }
        }
        __syncthreads();

        // ---- S = Q K^T : warp computes 16 rows x 32 q (2 frags) ----
        {
            FragC sacc[2];
            wmma::fill_fragment(sacc[0], 0.0f);
            wmma::fill_fragment(sacc[1], 0.0f);
#pragma unroll
            for (int d0 = 0; d0 < HS; d0 += 16) {
                FragA a_hi, a_lo;
                wmma::load_matrix_sync(a_hi, &qs_hi[(wm * 16) * QKSTR + d0], QKSTR);
                wmma::load_matrix_sync(a_lo, &qs_lo[(wm * 16) * QKSTR + d0], QKSTR);
#pragma unroll
                for (int nt = 0; nt < 2; nt++) {
                    int q0 = wn * 32 + nt * 16;
                    FragBT b_hi, b_lo;
                    wmma::load_matrix_sync(b_hi, &ks_hi[q0 * QKSTR + d0], QKSTR);
                    wmma::load_matrix_sync(b_lo, &ks_lo[q0 * QKSTR + d0], QKSTR);
                    wmma::mma_sync(sacc[nt], a_hi, b_hi, sacc[nt]);
                    wmma::mma_sync(sacc[nt], a_hi, b_lo, sacc[nt]);
                    wmma::mma_sync(sacc[nt], a_lo, b_hi, sacc[nt]);
                }
            }
#pragma unroll
            for (int nt = 0; nt < 2; nt++)
                wmma::store_matrix_sync(&ss[(wm * 16) * SSTR + wn * 32 + nt * 16],
                                        sacc[nt], SSTR, wmma::mem_row_major);
        }
        __syncthreads();

        // ---- softmax over q (128): row = t>>3, 8 lanes/row, 16 q each ----
        {
            const int row = t >> 3;
            const int tb  = t & 7;
            float* sr = &ss[row * SSTR];
            float v[16];
#pragma unroll
            for (int c = 0; c < 16; c++) v[c] = sr[c * 8 + tb];
            float m = v[0];
#pragma unroll
            for (int c = 1; c < 16; c++) m = fmaxf(m, v[c]);
#pragma unroll
            for (int msk = 1; msk < 8; msk <<= 1)
                m = fmaxf(m, __shfl_xor_sync(0xffffffffu, m, msk));
            float sum = 0.f;
#pragma unroll
            for (int c = 0; c < 16; c++) { v[c] = __expf(v[c] - m); sum += v[c]; }
#pragma unroll
            for (int msk = 1; msk < 8; msk <<= 1)
                sum += __shfl_xor_sync(0xffffffffu, sum, msk);
            float inv = 1.0f / sum;
#pragma unroll
            for (int c = 0; c < 16; c++) {
                __nv_bfloat16 h, l;
                split2(v[c] * inv, h, l);
                ps_hi[row * PBSTR + c * 8 + tb] = h;
                ps_lo[row * PBSTR + c * 8 + tb] = l;
            }
        }
        __syncthreads();

        // ---- O += P V : warp 16x16, persists over i ----
#pragma unroll
        for (int kk = 0; kk < 128; kk += 16) {
            FragA a_hi, a_lo;
            wmma::load_matrix_sync(a_hi, &ps_hi[(wm * 16) * PBSTR + kk], PBSTR);
            wmma::load_matrix_sync(a_lo, &ps_lo[(wm * 16) * PBSTR + kk], PBSTR);
            FragB b_hi, b_lo;
            wmma::load_matrix_sync(b_hi, &vs_hi[kk * QKSTR + wn * 16], QKSTR);
            wmma::load_matrix_sync(b_lo, &vs_lo[kk * QKSTR + wn * 16], QKSTR);
            wmma::mma_sync(oacc, a_hi, b_hi, oacc);
            wmma::mma_sync(oacc, a_hi, b_lo, oacc);
            wmma::mma_sync(oacc, a_lo, b_hi, oacc);
        }
    }

    wmma::store_matrix_sync(&out[(size_t)(qrow + wm * 16) * HS + wn * 16],
                            oacc, HS, wmma::mem_row_major);
}

// ---------------------------------------------------------------------------
extern "C" void kernel_launch(void* const* d_in, const int* in_sizes, int n_in,
                              void* d_out, int out_size)
{
    const float* x  = (const float*)d_in[0];
    const float* Wq = (const float*)d_in[1];
    const float* Wk = (const float*)d_in[2];
    const float* Wv = (const float*)d_in[3];
    float* out = (float*)d_out;

    qkv_kernel<<<dim3(512, 3), 512>>>(x, Wq, Wk, Wv);

    size_t smemB = (size_t)64 * SSTR * sizeof(float)
                 + (size_t)(2 * 64 * QKSTR + 4 * 128 * QKSTR + 2 * 64 * PBSTR)
                   * sizeof(__nv_bfloat16);
    cudaFuncSetAttribute(attn_kernel, cudaFuncAttributeMaxDynamicSharedMemorySize,
                         (int)smemB);
    attn_kernel<<<1024, 512, smemB>>>(out);
}

// round 9
// speedup vs baseline: 2.6621x; 1.0725x over previous
#include <cuda_runtime.h>
#include <cuda_bf16.h>
#include <mma.h>
#include <cstdint>

using namespace nvcuda;

// Shapes: n=8, b=64, h=128, f=256, hs=64
#define N_SEQ 8
#define B_DIM 64
#define H_DIM 128
#define F_DIM 256
#define HS 64
#define M_TOTAL (N_SEQ * B_DIM * H_DIM)   // 65536 rows

// Pre-split bf16 hi/lo Q,K,V (Q pre-scaled by 1/16)
__device__ __nv_bfloat16 g_Qh[M_TOTAL * HS], g_Ql[M_TOTAL * HS];
__device__ __nv_bfloat16 g_Kh[M_TOTAL * HS], g_Kl[M_TOTAL * HS];
__device__ __nv_bfloat16 g_Vh[M_TOTAL * HS], g_Vl[M_TOTAL * HS];

typedef wmma::fragment<wmma::matrix_a, 16, 16, 16, __nv_bfloat16, wmma::row_major> FragA;
typedef wmma::fragment<wmma::matrix_b, 16, 16, 16, __nv_bfloat16, wmma::row_major> FragB;
typedef wmma::fragment<wmma::accumulator, 16, 16, 16, float> FragC;

__device__ __forceinline__ void split2(float x, __nv_bfloat16& h, __nv_bfloat16& l) {
    h = __float2bfloat16(x);
    l = __float2bfloat16(x - __bfloat162float(h));
}

__device__ __forceinline__ uint32_t smem_u32(const void* p) {
    uint32_t a;
    asm("{ .reg .u64 t; cvta.to.shared.u64 t, %1; cvt.u32.u64 %0, t; }" : "=r"(a) : "l"(p));
    return a;
}

// raw bf16 mma + ldmatrix
__device__ __forceinline__ void mma16816(float* c, const uint32_t* a,
                                         uint32_t b0, uint32_t b1) {
    asm volatile(
        "mma.sync.aligned.m16n8k16.row.col.f32.bf16.bf16.f32 "
        "{%0,%1,%2,%3},{%4,%5,%6,%7},{%8,%9},{%0,%1,%2,%3};"
        : "+f"(c[0]), "+f"(c[1]), "+f"(c[2]), "+f"(c[3])
        : "r"(a[0]), "r"(a[1]), "r"(a[2]), "r"(a[3]), "r"(b0), "r"(b1));
}
__device__ __forceinline__ void ldsm4(uint32_t& r0, uint32_t& r1, uint32_t& r2,
                                      uint32_t& r3, uint32_t addr) {
    asm volatile("ldmatrix.sync.aligned.m8n8.x4.shared.b16 {%0,%1,%2,%3}, [%4];"
                 : "=r"(r0), "=r"(r1), "=r"(r2), "=r"(r3) : "r"(addr));
}
__device__ __forceinline__ void ldsm4t(uint32_t& r0, uint32_t& r1, uint32_t& r2,
                                       uint32_t& r3, uint32_t addr) {
    asm volatile("ldmatrix.sync.aligned.m8n8.x4.trans.shared.b16 {%0,%1,%2,%3}, [%4];"
                 : "=r"(r0), "=r"(r1), "=r"(r2), "=r"(r3) : "r"(addr));
}

// ---------------------------------------------------------------------------
// Kernel A: QKV via bf16 wmma split-3, pre-split bf16 hi/lo outputs.
// grid (1024,3), block 256. Per CTA 64 rows x 64 cols. Warps 4M x 2N.
// ---------------------------------------------------------------------------
#define XSTR 40
#define WSTR 72

__global__ __launch_bounds__(256) void qkv_kernel(
    const float* __restrict__ x,
    const float* __restrict__ Wq,
    const float* __restrict__ Wk,
    const float* __restrict__ Wv)
{
    __shared__ __nv_bfloat16 xs_hi[64][XSTR], xs_lo[64][XSTR];
    __shared__ __nv_bfloat16 ws_hi[32][WSTR], ws_lo[32][WSTR];
    __shared__ float sbuf[8][16 * 20];

    const int t    = threadIdx.x;
    const int w    = t >> 5;
    const int lane = t & 31;
    const int wm   = w >> 1;
    const int wn   = w & 1;
    const int rowBase = blockIdx.x * 64;
    const int which = blockIdx.y;
    const float* __restrict__ W = (which == 0) ? Wq : (which == 1) ? Wk : Wv;
    __nv_bfloat16* __restrict__ outH = (which == 0) ? g_Qh : (which == 1) ? g_Kh : g_Vh;
    __nv_bfloat16* __restrict__ outL = (which == 0) ? g_Ql : (which == 1) ? g_Kl : g_Vl;
    const float inScale = (which == 0) ? 0.0625f : 1.0f;

    FragC acc[2];
    wmma::fill_fragment(acc[0], 0.0f);
    wmma::fill_fragment(acc[1], 0.0f);

    for (int k0 = 0; k0 < F_DIM; k0 += 32) {
        // x tile 64x32: 512 float4 tasks over 256 threads -> 2 iterations
#pragma unroll
        for (int p = 0; p < 2; p++) {
            int e = t + p * 256;
            int row = e >> 3;
            int lc  = (e & 7) * 4;
            float4 v = *(const float4*)&x[(size_t)(rowBase + row) * F_DIM + k0 + lc];
            v.x *= inScale; v.y *= inScale; v.z *= inScale; v.w *= inScale;
            __nv_bfloat16 h0,l0,h1,l1,h2,l2,h3,l3;
            split2(v.x,h0,l0); split2(v.y,h1,l1); split2(v.z,h2,l2); split2(v.w,h3,l3);
            *(__nv_bfloat162*)&xs_hi[row][lc]     = __nv_bfloat162(h0, h1);
            *(__nv_bfloat162*)&xs_hi[row][lc + 2] = __nv_bfloat162(h2, h3);
            *(__nv_bfloat162*)&xs_lo[row][lc]     = __nv_bfloat162(l0, l1);
            *(__nv_bfloat162*)&xs_lo[row][lc + 2] = __nv_bfloat162(l2, l3);
        }
#pragma unroll
        for (int p = 0; p < 2; p++) {   // W chunk 32x64
            int e = t + p * 256;
            int k  = e >> 4;
            int cg = (e & 15) * 4;
            float4 v = *(const float4*)&W[(size_t)(k0 + k) * HS + cg];
            __nv_bfloat16 h0,l0,h1,l1,h2,l2,h3,l3;
            split2(v.x,h0,l0); split2(v.y,h1,l1); split2(v.z,h2,l2); split2(v.w,h3,l3);
            *(__nv_bfloat162*)&ws_hi[k][cg]     = __nv_bfloat162(h0, h1);
            *(__nv_bfloat162*)&ws_hi[k][cg + 2] = __nv_bfloat162(h2, h3);
            *(__nv_bfloat162*)&ws_lo[k][cg]     = __nv_bfloat162(l0, l1);
            *(__nv_bfloat162*)&ws_lo[k][cg + 2] = __nv_bfloat162(l2, l3);
        }
        __syncthreads();

#pragma unroll
        for (int kk = 0; kk < 32; kk += 16) {
            FragA a_hi, a_lo;
            wmma::load_matrix_sync(a_hi, &xs_hi[wm * 16][kk], XSTR);
            wmma::load_matrix_sync(a_lo, &xs_lo[wm * 16][kk], XSTR);
#pragma unroll
            for (int nt = 0; nt < 2; nt++) {
                FragB b_hi, b_lo;
                wmma::load_matrix_sync(b_hi, &ws_hi[kk][wn * 32 + nt * 16], WSTR);
                wmma::load_matrix_sync(b_lo, &ws_lo[kk][wn * 32 + nt * 16], WSTR);
                wmma::mma_sync(acc[nt], a_hi, b_hi, acc[nt]);
                wmma::mma_sync(acc[nt], a_hi, b_lo, acc[nt]);
                wmma::mma_sync(acc[nt], a_lo, b_hi, acc[nt]);
            }
        }
        __syncthreads();
    }

#pragma unroll
    for (int nt = 0; nt < 2; nt++) {
        wmma::store_matrix_sync(&sbuf[w][0], acc[nt], 20, wmma::mem_row_major);
        __syncwarp();
        int r  = lane & 15;
        int cg = (lane >> 4) * 8;
        size_t gbase = (size_t)(rowBase + wm * 16 + r) * HS + wn * 32 + nt * 16 + cg;
        __nv_bfloat16 hh[8], ll[8];
#pragma unroll
        for (int c = 0; c < 8; c++)
            split2(sbuf[w][r * 20 + cg + c], hh[c], ll[c]);
#pragma unroll
        for (int c = 0; c < 8; c += 2) {
            *(__nv_bfloat162*)&outH[gbase + c] = __nv_bfloat162(hh[c], hh[c + 1]);
            *(__nv_bfloat162*)&outL[gbase + c] = __nv_bfloat162(ll[c], ll[c + 1]);
        }
        __syncwarp();
    }
}

// ---------------------------------------------------------------------------
// Kernel B: FA-style attention on raw bf16 mma.m16n8k16.
// grid 1024 = (j,b,half), block 128 (4 warps). Warp owns 16 q-rows x ALL keys.
// Q A-frags hoisted to registers; softmax in accumulator regs; P packed in
// regs (never in smem). K/V tiles in smem stride 72 (conflict-free ldmatrix).
// ---------------------------------------------------------------------------
#define KVS 72   // bf16 elements per row

__global__ __launch_bounds__(128) void attn_kernel(float* __restrict__ out)
{
    extern __shared__ __nv_bfloat16 sm[];
    __nv_bfloat16* kh = sm;
    __nv_bfloat16* kl = kh + 128 * KVS;
    __nv_bfloat16* vh = kl + 128 * KVS;
    __nv_bfloat16* vl = vh + 128 * KVS;

    const int t    = threadIdx.x;
    const int w    = t >> 5;
    const int lane = t & 31;
    const int g    = lane >> 2;
    const int tg   = lane & 3;
    const int j    = blockIdx.x & 7;
    const int b    = (blockIdx.x >> 3) & 63;
    const int half = blockIdx.x >> 9;
    const int qrow = (j * B_DIM + b) * H_DIM + half * 64;

    const uint32_t khb = smem_u32(kh), klb = smem_u32(kl);
    const uint32_t vhb = smem_u32(vh), vlb = smem_u32(vl);

    // lane-invariant ldmatrix offsets (bytes)
    const uint32_t aofs  = (uint32_t)(((lane & 15) * KVS + ((lane >> 4) << 3)) * 2);
    const uint32_t kmofs = (uint32_t)((((lane & 7) + ((lane >> 4) << 3)) * KVS
                                       + (((lane >> 3) & 1) << 3)) * 2);
    const uint32_t vmofs = (uint32_t)((((lane & 7) + (((lane >> 3) & 1) << 3)) * KVS
                                       + ((lane >> 4) << 3)) * 2);

    // ---- stage Q (64 rows) into vh/vl, then hoist A-frags to registers ----
#pragma unroll
    for (int p = 0; p < 8; p++) {
        int e = t + p * 128;            // 1024 uint4 tasks
        int arr = e >> 9;               // 0: hi, 1: lo
        int idx = e & 511;
        int row = idx >> 3;
        int ch  = idx & 7;
        const __nv_bfloat16* src = arr ? g_Ql : g_Qh;
        __nv_bfloat16* dst = arr ? vl : vh;
        *(uint4*)&dst[row * KVS + ch * 8] =
            *(const uint4*)&src[(size_t)(qrow + row) * HS + ch * 8];
    }
    __syncthreads();

    uint32_t qhf[4][4], qlf[4][4];
#pragma unroll
    for (int ks = 0; ks < 4; ks++) {
        uint32_t off = (uint32_t)((w * 16 * KVS + ks * 16) * 2);
        ldsm4(qhf[ks][0], qhf[ks][1], qhf[ks][2], qhf[ks][3], vhb + off + aofs);
        ldsm4(qlf[ks][0], qlf[ks][1], qlf[ks][2], qlf[ks][3], vlb + off + aofs);
    }

    float oacc[8][4];
#pragma unroll
    for (int nf = 0; nf < 8; nf++)
#pragma unroll
        for (int c = 0; c < 4; c++) oacc[nf][c] = 0.f;

    for (int i = 0; i < N_SEQ; i++) {
        __syncthreads();   // prev PV reads done (and Q-frag loads at i==0)
        const int kb0 = (i * B_DIM + b) * H_DIM;
#pragma unroll 8
        for (int p = 0; p < 32; p++) {
            int e = t + p * 128;        // 4096 uint4 tasks
            int arr = e >> 10;          // 0..3
            int idx = e & 1023;
            int row = idx >> 3;
            int ch  = idx & 7;
            const __nv_bfloat16* src = (arr == 0) ? g_Kh : (arr == 1) ? g_Kl
                                      : (arr == 2) ? g_Vh : g_Vl;
            __nv_bfloat16* dst = (arr == 0) ? kh : (arr == 1) ? kl
                                : (arr == 2) ? vh : vl;
            *(uint4*)&dst[row * KVS + ch * 8] =
                *(const uint4*)&src[(size_t)(kb0 + row) * HS + ch * 8];
        }
        __syncthreads();

        // ---- S = Q K^T : 16 rows x 128 keys in accumulator registers ----
        float sacc[16][4];
#pragma unroll
        for (int nf = 0; nf < 16; nf++)
#pragma unroll
            for (int c = 0; c < 4; c++) sacc[nf][c] = 0.f;

#pragma unroll
        for (int ks = 0; ks < 4; ks++) {
#pragma unroll
            for (int nfp = 0; nfp < 8; nfp++) {
                uint32_t off = (uint32_t)((nfp * 16 * KVS + ks * 16) * 2);
                uint32_t bh0, bh1, bh2, bh3, bl0, bl1, bl2, bl3;
                ldsm4(bh0, bh1, bh2, bh3, khb + off + kmofs);
                ldsm4(bl0, bl1, bl2, bl3, klb + off + kmofs);
                mma16816(sacc[2 * nfp],     qhf[ks], bh0, bh1);
                mma16816(sacc[2 * nfp],     qlf[ks], bh0, bh1);
                mma16816(sacc[2 * nfp],     qhf[ks], bl0, bl1);
                mma16816(sacc[2 * nfp + 1], qhf[ks], bh2, bh3);
                mma16816(sacc[2 * nfp + 1], qlf[ks], bh2, bh3);
                mma16816(sacc[2 * nfp + 1], qhf[ks], bl2, bl3);
            }
        }

        // ---- softmax in registers (rows g and g+8 of this warp's 16) ----
        float mx_a = sacc[0][0], mx_b = sacc[0][2];
#pragma unroll
        for (int nf = 0; nf < 16; nf++) {
            mx_a = fmaxf(mx_a, fmaxf(sacc[nf][0], sacc[nf][1]));
            mx_b = fmaxf(mx_b, fmaxf(sacc[nf][2], sacc[nf][3]));
        }
        mx_a = fmaxf(mx_a, __shfl_xor_sync(0xffffffffu, mx_a, 1));
        mx_a = fmaxf(mx_a, __shfl_xor_sync(0xffffffffu, mx_a, 2));
        mx_b = fmaxf(mx_b, __shfl_xor_sync(0xffffffffu, mx_b, 1));
        mx_b = fmaxf(mx_b, __shfl_xor_sync(0xffffffffu, mx_b, 2));
        float sum_a = 0.f, sum_b = 0.f;
#pragma unroll
        for (int nf = 0; nf < 16; nf++) {
            sacc[nf][0] = __expf(sacc[nf][0] - mx_a);
            sacc[nf][1] = __expf(sacc[nf][1] - mx_a);
            sacc[nf][2] = __expf(sacc[nf][2] - mx_b);
            sacc[nf][3] = __expf(sacc[nf][3] - mx_b);
            sum_a += sacc[nf][0] + sacc[nf][1];
            sum_b += sacc[nf][2] + sacc[nf][3];
        }
        sum_a += __shfl_xor_sync(0xffffffffu, sum_a, 1);
        sum_a += __shfl_xor_sync(0xffffffffu, sum_a, 2);
        sum_b += __shfl_xor_sync(0xffffffffu, sum_b, 1);
        sum_b += __shfl_xor_sync(0xffffffffu, sum_b, 2);
        const float inv_a = 1.0f / sum_a, inv_b = 1.0f / sum_b;

        // ---- pack P (hi/lo) into A-fragment registers: zero smem traffic ----
        uint32_t pah[8][4], pal[8][4];
#pragma unroll
        for (int s = 0; s < 8; s++) {
#pragma unroll
            for (int hf = 0; hf < 2; hf++) {
                int nf = 2 * s + hf;
                float p0 = sacc[nf][0] * inv_a, p1 = sacc[nf][1] * inv_a;
                float p2 = sacc[nf][2] * inv_b, p3 = sacc[nf][3] * inv_b;
                __nv_bfloat16 h0,l0,h1,l1,h2,l2,h3,l3;
                split2(p0,h0,l0); split2(p1,h1,l1);
                split2(p2,h2,l2); split2(p3,h3,l3);
                __nv_bfloat162 ph01(h0,h1), ph23(h2,h3), pl01(l0,l1), pl23(l2,l3);
                pah[s][2 * hf]     = *(uint32_t*)&ph01;
                pah[s][2 * hf + 1] = *(uint32_t*)&ph23;
                pal[s][2 * hf]     = *(uint32_t*)&pl01;
                pal[s][2 * hf + 1] = *(uint32_t*)&pl23;
            }
        }

        // ---- O += P V (split-3), V via ldmatrix.trans ----
#pragma unroll
        for (int s = 0; s < 8; s++) {
#pragma unroll
            for (int nfp = 0; nfp < 4; nfp++) {
                uint32_t off = (uint32_t)((s * 16 * KVS + nfp * 16) * 2);
                uint32_t bh0, bh1, bh2, bh3, bl0, bl1, bl2, bl3;
                ldsm4t(bh0, bh1, bh2, bh3, vhb + off + vmofs);
                ldsm4t(bl0, bl1, bl2, bl3, vlb + off + vmofs);
                mma16816(oacc[2 * nfp],     pah[s], bh0, bh1);
                mma16816(oacc[2 * nfp],     pal[s], bh0, bh1);
                mma16816(oacc[2 * nfp],     pah[s], bl0, bl1);
                mma16816(oacc[2 * nfp + 1], pah[s], bh2, bh3);
                mma16816(oacc[2 * nfp + 1], pal[s], bh2, bh3);
                mma16816(oacc[2 * nfp + 1], pah[s], bl2, bl3);
            }
        }
    }

    // ---- write O ----
#pragma unroll
    for (int nf = 0; nf < 8; nf++) {
        size_t r0 = (size_t)(qrow + w * 16 + g) * HS + nf * 8 + 2 * tg;
        size_t r1 = (size_t)(qrow + w * 16 + g + 8) * HS + nf * 8 + 2 * tg;
        *(float2*)&out[r0] = make_float2(oacc[nf][0], oacc[nf][1]);
        *(float2*)&out[r1] = make_float2(oacc[nf][2], oacc[nf][3]);
    }
}

// ---------------------------------------------------------------------------
extern "C" void kernel_launch(void* const* d_in, const int* in_sizes, int n_in,
                              void* d_out, int out_size)
{
    const float* x  = (const float*)d_in[0];
    const float* Wq = (const float*)d_in[1];
    const float* Wk = (const float*)d_in[2];
    const float* Wv = (const float*)d_in[3];
    float* out = (float*)d_out;

    qkv_kernel<<<dim3(1024, 3), 256>>>(x, Wq, Wk, Wv);

    int smemB = 4 * 128 * KVS * (int)sizeof(__nv_bfloat16);   // 73728
    cudaFuncSetAttribute(attn_kernel, cudaFuncAttributeMaxDynamicSharedMemorySize, smemB);
    attn_kernel<<<1024, 128, smemB>>>(out);
}